// round 1
// baseline (speedup 1.0000x reference)
#include <cuda_runtime.h>
#include <math.h>

#define BATCH 8
#define SEQ   4096
#define DIM   1024
#define SDIM  64
#define SHIFTN 2048
#define MTOT  (BATCH*SEQ)   /* 32768 */

// Scratch (static device globals: allowed; no cudaMalloc anywhere)
__device__ float g_xs[(size_t)MTOT * DIM];     // x_shift -> xn (in place), 128 MB
__device__ float g_k[(size_t)MTOT * SDIM];     // 8 MB
__device__ float g_v[(size_t)MTOT * SDIM];     // 8 MB
__device__ float g_wkv[(size_t)MTOT * SDIM];   // 8 MB
__device__ float g_states[(size_t)MTOT * SDIM];// 8 MB

// ---------------------------------------------------------------------------
// Kernel 1: x_shift = (x_cat @ W_shift^T) * gate + x * (1-gate)
// C[m,e], m = b*T + t, A-row = x[b, (t+2048)%4096, :], B-row = W_shift[e, :]
// 128x128 tile, BK=16, 256 threads, 8x8 register tile.
// ---------------------------------------------------------------------------
__global__ __launch_bounds__(256, 2)
void k_shift_gemm(const float* __restrict__ x, const float* __restrict__ Wsh,
                  const float* __restrict__ shift_gate)
{
    __shared__ float As[16][128];
    __shared__ float Bs[16][128];
    const int tid = threadIdx.x;
    const int m0 = blockIdx.x * 128;
    const int e0 = blockIdx.y * 128;
    const int ty = tid >> 4;     // 0..15
    const int tx = tid & 15;     // 0..15

    const float* aptr[2];
    const float* bptr[2];
    int arow[2], ac4[2];
#pragma unroll
    for (int i = 0; i < 2; i++) {
        int idx = tid + 256 * i;      // 0..511
        int row = idx >> 2;           // 0..127
        int c4  = idx & 3;            // 0..3
        arow[i] = row; ac4[i] = c4;
        int m = m0 + row;
        int b = m >> 12;              // /4096
        int t = m & 4095;
        int ts = t + SHIFTN; if (ts >= SEQ) ts -= SEQ;
        aptr[i] = x + ((size_t)(b * SEQ + ts)) * DIM + c4 * 4;
        bptr[i] = Wsh + (size_t)(e0 + row) * DIM + c4 * 4;
    }

    float acc[8][8];
#pragma unroll
    for (int i = 0; i < 8; i++)
#pragma unroll
        for (int j = 0; j < 8; j++) acc[i][j] = 0.f;

    for (int k0 = 0; k0 < DIM; k0 += 16) {
#pragma unroll
        for (int i = 0; i < 2; i++) {
            float4 av = *(const float4*)(aptr[i] + k0);
            int c = ac4[i] * 4, r = arow[i];
            As[c + 0][r] = av.x; As[c + 1][r] = av.y;
            As[c + 2][r] = av.z; As[c + 3][r] = av.w;
            float4 bv = *(const float4*)(bptr[i] + k0);
            Bs[c + 0][r] = bv.x; Bs[c + 1][r] = bv.y;
            Bs[c + 2][r] = bv.z; Bs[c + 3][r] = bv.w;
        }
        __syncthreads();
#pragma unroll
        for (int kk = 0; kk < 16; kk++) {
            float ra[8], rb[8];
            *(float4*)(ra)     = *(const float4*)&As[kk][ty * 8];
            *(float4*)(ra + 4) = *(const float4*)&As[kk][ty * 8 + 4];
            *(float4*)(rb)     = *(const float4*)&Bs[kk][tx * 8];
            *(float4*)(rb + 4) = *(const float4*)&Bs[kk][tx * 8 + 4];
#pragma unroll
            for (int i = 0; i < 8; i++)
#pragma unroll
                for (int j = 0; j < 8; j++)
                    acc[i][j] = fmaf(ra[i], rb[j], acc[i][j]);
        }
        __syncthreads();
    }

    // Epilogue: gated blend with (un-shifted) x, write to g_xs.
#pragma unroll
    for (int j = 0; j < 8; j++) {
        int e = e0 + tx * 8 + j;
        float g  = 1.f / (1.f + expf(-shift_gate[e]));
        float gi = 1.f - g;
#pragma unroll
        for (int i = 0; i < 8; i++) {
            int m = m0 + ty * 8 + i;
            float xv = x[(size_t)m * DIM + e];
            g_xs[(size_t)m * DIM + e] = acc[i][j] * g + xv * gi;
        }
    }
}

// ---------------------------------------------------------------------------
// Kernel 2: per-token layernorm, in place on g_xs
// ---------------------------------------------------------------------------
__inline__ __device__ float warp_sum(float v) {
#pragma unroll
    for (int o = 16; o > 0; o >>= 1) v += __shfl_xor_sync(0xffffffffu, v, o);
    return v;
}

__global__ __launch_bounds__(256)
void k_layernorm(const float* __restrict__ lnw, const float* __restrict__ lnb)
{
    int m = blockIdx.x;
    int tid = threadIdx.x;
    float4* row = (float4*)(g_xs + (size_t)m * DIM);
    float4 v = row[tid];
    float s  = v.x + v.y + v.z + v.w;
    float ss = fmaf(v.x, v.x, fmaf(v.y, v.y, fmaf(v.z, v.z, v.w * v.w)));
    s = warp_sum(s); ss = warp_sum(ss);
    __shared__ float sh_s[8], sh_ss[8];
    int wid = tid >> 5, lane = tid & 31;
    if (lane == 0) { sh_s[wid] = s; sh_ss[wid] = ss; }
    __syncthreads();
    if (wid == 0) {
        float a = (lane < 8) ? sh_s[lane] : 0.f;
        float b = (lane < 8) ? sh_ss[lane] : 0.f;
        a = warp_sum(a); b = warp_sum(b);
        if (lane == 0) { sh_s[0] = a; sh_ss[0] = b; }
    }
    __syncthreads();
    float mu  = sh_s[0] * (1.f / DIM);
    float var = sh_ss[0] * (1.f / DIM) - mu * mu;
    float rstd = rsqrtf(var + 1e-5f);
    float4 w4 = ((const float4*)lnw)[tid];
    float4 b4 = ((const float4*)lnb)[tid];
    v.x = (v.x - mu) * rstd * w4.x + b4.x;
    v.y = (v.y - mu) * rstd * w4.y + b4.y;
    v.z = (v.z - mu) * rstd * w4.z + b4.z;
    v.w = (v.w - mu) * rstd * w4.w + b4.w;
    row[tid] = v;
}

// ---------------------------------------------------------------------------
// Kernel 3: k = xn @ W_key^T, v = xn @ W_value^T (stacked N=128 GEMM)
// ---------------------------------------------------------------------------
__global__ __launch_bounds__(256, 2)
void k_kv_gemm(const float* __restrict__ Wk, const float* __restrict__ Wv)
{
    __shared__ float As[16][128];
    __shared__ float Bs[16][128];
    const int tid = threadIdx.x;
    const int m0 = blockIdx.x * 128;
    const int ty = tid >> 4, tx = tid & 15;

    const float* aptr[2];
    const float* bptr[2];
    int arow[2], ac4[2];
#pragma unroll
    for (int i = 0; i < 2; i++) {
        int idx = tid + 256 * i;
        int row = idx >> 2;
        int c4  = idx & 3;
        arow[i] = row; ac4[i] = c4;
        aptr[i] = g_xs + (size_t)(m0 + row) * DIM + c4 * 4;
        const float* base = (row < 64) ? (Wk + (size_t)row * DIM)
                                       : (Wv + (size_t)(row - 64) * DIM);
        bptr[i] = base + c4 * 4;
    }

    float acc[8][8];
#pragma unroll
    for (int i = 0; i < 8; i++)
#pragma unroll
        for (int j = 0; j < 8; j++) acc[i][j] = 0.f;

    for (int k0 = 0; k0 < DIM; k0 += 16) {
#pragma unroll
        for (int i = 0; i < 2; i++) {
            float4 av = *(const float4*)(aptr[i] + k0);
            int c = ac4[i] * 4, r = arow[i];
            As[c + 0][r] = av.x; As[c + 1][r] = av.y;
            As[c + 2][r] = av.z; As[c + 3][r] = av.w;
            float4 bv = *(const float4*)(bptr[i] + k0);
            Bs[c + 0][r] = bv.x; Bs[c + 1][r] = bv.y;
            Bs[c + 2][r] = bv.z; Bs[c + 3][r] = bv.w;
        }
        __syncthreads();
#pragma unroll
        for (int kk = 0; kk < 16; kk++) {
            float ra[8], rb[8];
            *(float4*)(ra)     = *(const float4*)&As[kk][ty * 8];
            *(float4*)(ra + 4) = *(const float4*)&As[kk][ty * 8 + 4];
            *(float4*)(rb)     = *(const float4*)&Bs[kk][tx * 8];
            *(float4*)(rb + 4) = *(const float4*)&Bs[kk][tx * 8 + 4];
#pragma unroll
            for (int i = 0; i < 8; i++)
#pragma unroll
                for (int j = 0; j < 8; j++)
                    acc[i][j] = fmaf(ra[i], rb[j], acc[i][j]);
        }
        __syncthreads();
    }

#pragma unroll
    for (int j = 0; j < 8; j++) {
        int e = tx * 8 + j;
#pragma unroll
        for (int i = 0; i < 8; i++) {
            int m = m0 + ty * 8 + i;
            if (e < 64) g_k[(size_t)m * SDIM + e]        = acc[i][j];
            else        g_v[(size_t)m * SDIM + (e - 64)] = acc[i][j];
        }
    }
}

// ---------------------------------------------------------------------------
// Kernel 4: wkv = exp(-exp(time_first[s]) * sigmoid(k)) * v
// ---------------------------------------------------------------------------
__global__ void k_wkv(const float* __restrict__ time_first)
{
    int i = blockIdx.x * blockDim.x + threadIdx.x;
    if (i >= MTOT * SDIM) return;
    int s = i & (SDIM - 1);
    float tf = expf(time_first[s]);
    float kk = g_k[i];
    float vv = g_v[i];
    float sig = 1.f / (1.f + expf(-kk));
    g_wkv[i] = expf(-tf * sig) * vv;
}

// ---------------------------------------------------------------------------
// Kernel 5: recurrence state = state*w + wkv_t over T; also write last_state
// ---------------------------------------------------------------------------
__global__ void k_recur(const float* __restrict__ time_decay,
                        float* __restrict__ last_out)
{
    int b = blockIdx.x;
    int s = threadIdx.x;
    float w = expf(time_decay[s]);
    const float* wp = g_wkv    + (size_t)b * SEQ * SDIM + s;
    float*       sp = g_states + (size_t)b * SEQ * SDIM + s;
    float st = 0.f;
#pragma unroll 8
    for (int t = 0; t < SEQ; t++) {
        st = fmaf(st, w, wp[(size_t)t * SDIM]);
        sp[(size_t)t * SDIM] = st;
    }
    last_out[b * SDIM + s] = st;
}

// ---------------------------------------------------------------------------
// Kernel 6: out[m,d] = sum_s states[m,s] * W_output[d,s]   (K=64)
// Tile: 32 tokens x 128 d, 256 threads, 4x4 per thread.
// ---------------------------------------------------------------------------
__global__ __launch_bounds__(256)
void k_output(const float* __restrict__ Wo, float* __restrict__ out)
{
    __shared__ float Ss[64][32];
    __shared__ float Ws[64][128];
    int m0 = blockIdx.x * 32;
    int d0 = blockIdx.y * 128;
    int tid = threadIdx.x;

    // states tile: 32 x 64 = 512 float4, 2 per thread
#pragma unroll
    for (int i = 0; i < 2; i++) {
        int idx = tid + 256 * i;     // 0..511
        int row = idx >> 4;          // 0..31
        int s4  = idx & 15;
        float4 v = *(const float4*)(g_states + (size_t)(m0 + row) * SDIM + s4 * 4);
        Ss[s4 * 4 + 0][row] = v.x; Ss[s4 * 4 + 1][row] = v.y;
        Ss[s4 * 4 + 2][row] = v.z; Ss[s4 * 4 + 3][row] = v.w;
    }
    // Wo tile: 128 x 64 = 2048 float4, 8 per thread
#pragma unroll
    for (int i = 0; i < 8; i++) {
        int idx = tid + 256 * i;     // 0..2047
        int row = idx >> 4;          // 0..127
        int s4  = idx & 15;
        float4 v = *(const float4*)(Wo + (size_t)(d0 + row) * SDIM + s4 * 4);
        Ws[s4 * 4 + 0][row] = v.x; Ws[s4 * 4 + 1][row] = v.y;
        Ws[s4 * 4 + 2][row] = v.z; Ws[s4 * 4 + 3][row] = v.w;
    }
    __syncthreads();

    int tr = (tid >> 5) * 4;     // 0..28 (token rows)
    int tc = (tid & 31) * 4;     // 0..124 (d cols)
    float acc[4][4];
#pragma unroll
    for (int i = 0; i < 4; i++)
#pragma unroll
        for (int j = 0; j < 4; j++) acc[i][j] = 0.f;

#pragma unroll
    for (int s = 0; s < 64; s++) {
        float ra[4], rb[4];
        *(float4*)ra = *(const float4*)&Ss[s][tr];
        *(float4*)rb = *(const float4*)&Ws[s][tc];
#pragma unroll
        for (int i = 0; i < 4; i++)
#pragma unroll
            for (int j = 0; j < 4; j++)
                acc[i][j] = fmaf(ra[i], rb[j], acc[i][j]);
    }

#pragma unroll
    for (int i = 0; i < 4; i++) {
        float4 o;
        o.x = acc[i][0]; o.y = acc[i][1]; o.z = acc[i][2]; o.w = acc[i][3];
        *(float4*)(out + (size_t)(m0 + tr + i) * DIM + d0 + tc) = o;
    }
}

// ---------------------------------------------------------------------------
extern "C" void kernel_launch(void* const* d_in, const int* in_sizes, int n_in,
                              void* d_out, int out_size)
{
    const float* x   = (const float*)d_in[0];
    const float* td  = (const float*)d_in[1];
    const float* tf  = (const float*)d_in[2];
    const float* Wk  = (const float*)d_in[3];
    const float* Wv  = (const float*)d_in[4];
    const float* Wo  = (const float*)d_in[5];
    const float* Wsh = (const float*)d_in[6];
    const float* sg  = (const float*)d_in[7];
    const float* lnw = (const float*)d_in[8];
    const float* lnb = (const float*)d_in[9];

    float* out  = (float*)d_out;                    // (B,T,D)
    float* last = out + (size_t)MTOT * DIM;         // (B,S) appended

    dim3 g1(MTOT / 128, DIM / 128);
    k_shift_gemm<<<g1, 256>>>(x, Wsh, sg);

    k_layernorm<<<MTOT, 256>>>(lnw, lnb);

    k_kv_gemm<<<MTOT / 128, 256>>>(Wk, Wv);

    k_wkv<<<(MTOT * SDIM + 255) / 256, 256>>>(tf);

    k_recur<<<BATCH, SDIM>>>(td, last);

    dim3 g6(MTOT / 32, DIM / 128);
    k_output<<<g6, 256>>>(Wo, out);
}